// round 1
// baseline (speedup 1.0000x reference)
#include <cuda_runtime.h>

#define BB 16
#define SS 2048
#define FF 64
#define RR (BB*SS)
#define CH 16
#define CHM (SS/CH)

// ---- scratch (device globals; no allocations allowed) ----
__device__ __align__(128) float g_ts[SS];       // sorted template
__device__ __align__(128) int   g_perm[SS];     // sort permutation
__device__ __align__(128) float g_us[SS];       // exp(t) sorted order
__device__ __align__(128) float g_vs[SS];       // exp(-t) sorted order
__device__ __align__(128) float g_uo[SS];       // exp(t) original order
__device__ __align__(128) float g_vo[SS];       // exp(-t) original order
__device__ __align__(128) float g_P[SS+1];      // prefix of exp(ts)
__device__ __align__(128) float g_Q[SS+1];      // suffix of exp(-ts)
__device__ __align__(128) float g_A[RR];        // exp(-s)/Z per row
__device__ __align__(128) float g_Bc[RR];       // exp(s)/Z per row
__device__ __align__(128) int   g_kk[RR];       // split index per row
__device__ __align__(128) float g_fs[(size_t)BB*SS*FF];       // feature gathered into sorted order
__device__ __align__(128) float g_G[(size_t)BB*(SS+1)*FF];    // prefix of u*f
__device__ __align__(128) float g_H[(size_t)BB*(SS+1)*FF];    // suffix of v*f
__device__ __align__(128) float g_pu[BB*CH*FF];
__device__ __align__(128) float g_pv[BB*CH*FF];

// K0: sort template (bitonic, 1 block), exps, scalar prefix/suffix scans
__global__ void k0_sort(const float* __restrict__ tmpl) {
    __shared__ float kv[SS];
    __shared__ int   id[SS];
    __shared__ float c[1024];
    int tid = threadIdx.x;
    for (int i = tid; i < SS; i += 1024) { kv[i] = tmpl[i]; id[i] = i; }
    for (int i = tid; i < SS; i += 1024) {
        float t = tmpl[i];
        g_uo[i] = __expf(t);
        g_vo[i] = __expf(-t);
    }
    __syncthreads();
    // bitonic sort ascending
    for (int k2 = 2; k2 <= SS; k2 <<= 1) {
        for (int j = k2 >> 1; j > 0; j >>= 1) {
            for (int i = tid; i < SS; i += 1024) {
                int ixj = i ^ j;
                if (ixj > i) {
                    bool up = ((i & k2) == 0);
                    float a = kv[i], b = kv[ixj];
                    if ((a > b) == up) {
                        kv[i] = b; kv[ixj] = a;
                        int ta = id[i]; id[i] = id[ixj]; id[ixj] = ta;
                    }
                }
            }
            __syncthreads();
        }
    }
    for (int i = tid; i < SS; i += 1024) {
        g_ts[i] = kv[i]; g_perm[i] = id[i];
        g_us[i] = __expf(kv[i]); g_vs[i] = __expf(-kv[i]);
    }
    __syncthreads();

    // P: exclusive prefix of exp(ts). Pair-wise + Hillis-Steele over 1024 partials.
    {
        float e0 = __expf(kv[2*tid]), e1 = __expf(kv[2*tid+1]);
        float cc = e0 + e1;
        c[tid] = cc; __syncthreads();
        for (int off = 1; off < 1024; off <<= 1) {
            float tv = c[tid];
            if (tid >= off) tv += c[tid - off];
            __syncthreads(); c[tid] = tv; __syncthreads();
        }
        float incl = c[tid];
        float excl = incl - cc;
        g_P[2*tid]   = excl;
        g_P[2*tid+1] = excl + e0;
        if (tid == 1023) g_P[SS] = incl;
        __syncthreads();
    }
    // Q: direct suffix scan of exp(-ts) (reversed prefix; avoids total-minus-prefix cancellation)
    {
        float dr0 = __expf(-kv[SS-1-2*tid]);   // reversed element 2*tid
        float dr1 = __expf(-kv[SS-2-2*tid]);   // reversed element 2*tid+1
        float cc = dr0 + dr1;
        c[tid] = cc; __syncthreads();
        for (int off = 1; off < 1024; off <<= 1) {
            float tv = c[tid];
            if (tid >= off) tv += c[tid - off];
            __syncthreads(); c[tid] = tv; __syncthreads();
        }
        float incl = c[tid];
        float excl = incl - cc;
        // E[p] = sum of first p reversed elems; Q[k] = E[SS-k]
        g_Q[SS - 2*tid]     = excl;        // p = 2*tid
        g_Q[SS - (2*tid+1)] = excl + dr0;  // p = 2*tid+1
        if (tid == 1023) g_Q[0] = incl;    // p = SS
    }
}

// K1: per-row coefficients (binary search + Z)
__global__ void k1_coeff(const float* __restrict__ score) {
    int r = blockIdx.x * blockDim.x + threadIdx.x;
    if (r >= RR) return;
    float s = score[r];
    int lo = 0, hi = SS;
    while (lo < hi) {
        int mid = (lo + hi) >> 1;
        if (g_ts[mid] <= s) lo = mid + 1; else hi = mid;
    }
    int k = lo;
    float e  = __expf(-s);
    float ei = __expf(s);
    float Z = e * g_P[k] + ei * g_Q[k];
    float inv = 1.0f / Z;
    g_A[r]  = e * inv;
    g_Bc[r] = ei * inv;
    g_kk[r] = k;
}

// K2: gather feature rows into template-sorted order
__global__ void k2_gather(const float* __restrict__ feat) {
    int e = blockIdx.x * blockDim.x + threadIdx.x;   // over B*S*F = 2^21
    int f = e & (FF - 1);
    int m = (e >> 6) & (SS - 1);
    int b = e >> 17;
    int src = (b << 11) + g_perm[m];
    g_fs[e] = feat[(size_t)src * FF + f];
}

// K3: per-chunk partial sums of u*f (fwd) and v*f (suffix parts)
__global__ void k3_part() {
    int b = blockIdx.x, ch = blockIdx.y, f = threadIdx.x;
    int m0 = ch * CHM;
    float su = 0.f, sv = 0.f;
    const float* fsb = g_fs + (size_t)b * SS * FF;
    #pragma unroll 4
    for (int m = m0; m < m0 + CHM; ++m) {
        float x = fsb[(size_t)m * FF + f];
        su += g_us[m] * x;
        sv += g_vs[m] * x;
    }
    g_pu[(b*CH + ch)*FF + f] = su;
    g_pv[(b*CH + ch)*FF + f] = sv;
}

// K5: write full G (exclusive prefix of u*f) and H (inclusive suffix of v*f)
__global__ void k5_write() {
    int b = blockIdx.x, ch = blockIdx.y, f = threadIdx.x;
    float offU = 0.f, offV = 0.f;
    for (int c2 = 0; c2 < ch; ++c2)      offU += g_pu[(b*CH + c2)*FF + f];
    for (int c2 = ch+1; c2 < CH; ++c2)   offV += g_pv[(b*CH + c2)*FF + f];
    int m0 = ch * CHM;
    const float* fsb = g_fs + (size_t)b * SS * FF;
    float* Gb = g_G + (size_t)b * (SS+1) * FF;
    float* Hb = g_H + (size_t)b * (SS+1) * FF;
    float acc = offU;
    #pragma unroll 4
    for (int m = m0; m < m0 + CHM; ++m) {
        Gb[(size_t)m * FF + f] = acc;
        acc += g_us[m] * fsb[(size_t)m * FF + f];
    }
    float accV = offV;
    #pragma unroll 4
    for (int m = m0 + CHM - 1; m >= m0; --m) {
        accV += g_vs[m] * fsb[(size_t)m * FF + f];
        Hb[(size_t)m * FF + f] = accV;
    }
    if (ch == CH - 1) {
        Gb[(size_t)SS * FF + f] = acc + offU - offU; // acc already includes offU; value = full prefix
        Hb[(size_t)SS * FF + f] = 0.f;
    }
}

// K6: main — write path row (min(A*u, B*v)) + aligned row (A*G[k] + B*H[k])
__global__ void k6_main(float* __restrict__ out) {
    int warp = threadIdx.x >> 5, lane = threadIdx.x & 31;
    int r = blockIdx.x * 8 + warp;
    float A  = g_A[r];
    float Bv = g_Bc[r];
    float* aligned = out;
    float* path = out + (size_t)RR * FF;
    float* prow = path + (size_t)r * SS;
    #pragma unroll 4
    for (int j = lane * 4; j < SS; j += 128) {
        float4 u = *reinterpret_cast<const float4*>(g_uo + j);
        float4 v = *reinterpret_cast<const float4*>(g_vo + j);
        float4 p;
        p.x = fminf(A*u.x, Bv*v.x);
        p.y = fminf(A*u.y, Bv*v.y);
        p.z = fminf(A*u.z, Bv*v.z);
        p.w = fminf(A*u.w, Bv*v.w);
        *reinterpret_cast<float4*>(prow + j) = p;
    }
    int k = g_kk[r];
    int b = r >> 11;
    const float* Gp = g_G + ((size_t)b * (SS+1) + k) * FF;
    const float* Hp = g_H + ((size_t)b * (SS+1) + k) * FF;
    float2 g2 = *reinterpret_cast<const float2*>(Gp + 2*lane);
    float2 h2 = *reinterpret_cast<const float2*>(Hp + 2*lane);
    float2 o;
    o.x = A*g2.x + Bv*h2.x;
    o.y = A*g2.y + Bv*h2.y;
    *reinterpret_cast<float2*>(aligned + (size_t)r * FF + 2*lane) = o;
}

extern "C" void kernel_launch(void* const* d_in, const int* in_sizes, int n_in,
                              void* d_out, int out_size) {
    const float* score = (const float*)d_in[0];   // [16,2048,1]
    const float* feat  = (const float*)d_in[1];   // [16,2048,64]
    const float* tmpl  = (const float*)d_in[2];   // [1,2048,1]
    float* out = (float*)d_out;                   // aligned [16,2048,64] then path [16,2048,2048]

    k0_sort<<<1, 1024>>>(tmpl);
    k1_coeff<<<RR/256, 256>>>(score);
    k2_gather<<<(BB*SS*FF)/256, 256>>>(feat);
    dim3 gpc(BB, CH);
    k3_part<<<gpc, FF>>>();
    k5_write<<<gpc, FF>>>();
    k6_main<<<RR/8, 256>>>(out);
}

// round 2
// speedup vs baseline: 1.9526x; 1.9526x over previous
#include <cuda_runtime.h>

#define BB 16
#define SS 2048
#define FF 64
#define RR (BB*SS)
#define CH 64
#define CHM (SS/CH)   // 32

// ---- scratch (device globals; no allocations allowed) ----
__device__ __align__(128) float g_ts[SS];       // sorted template
__device__ __align__(128) int   g_perm[SS];     // sort permutation (sorted -> original)
__device__ __align__(128) float g_us[SS];       // exp(t) sorted order
__device__ __align__(128) float g_vs[SS];       // exp(-t) sorted order
__device__ __align__(128) float g_uo[SS];       // exp(t) original order
__device__ __align__(128) float g_vo[SS];       // exp(-t) original order
__device__ __align__(128) float g_P[SS+1];      // exclusive prefix of exp(ts)
__device__ __align__(128) float g_Q[SS+1];      // inclusive suffix of exp(-ts)
__device__ __align__(128) float g_G[(size_t)BB*(SS+1)*FF];    // prefix of u*f (sorted order)
__device__ __align__(128) float g_H[(size_t)BB*(SS+1)*FF];    // suffix of v*f (sorted order)
__device__ __align__(128) float g_pu[BB*CH*FF];
__device__ __align__(128) float g_pv[BB*CH*FF];

// KA: rank sort (O(N^2), warp per element) + all exps.
// grid 256 x block 256 (8 warps/block, warp per template element)
__global__ void ka_rank(const float* __restrict__ tmpl) {
    __shared__ float sh[SS];
    int tid = threadIdx.x;
    for (int i = tid; i < SS; i += 256) sh[i] = tmpl[i];
    __syncthreads();
    int e = blockIdx.x * 8 + (tid >> 5);
    int lane = tid & 31;
    float t = sh[e];
    int cnt = 0;
    #pragma unroll 8
    for (int j = lane; j < SS; j += 32) {
        float tj = sh[j];
        cnt += (tj < t) || (tj == t && j < e);
    }
    #pragma unroll
    for (int o = 16; o; o >>= 1) cnt += __shfl_down_sync(0xffffffffu, cnt, o);
    if (lane == 0) {
        float u = __expf(t), v = __expf(-t);
        g_ts[cnt] = t; g_perm[cnt] = e;
        g_us[cnt] = u; g_vs[cnt] = v;
        g_uo[e]  = u; g_vo[e]  = v;
    }
}

// KB: P/Q scans over sorted exps (1 block, 1024 threads, Hillis-Steele)
__global__ void kb_scan() {
    __shared__ float c[1024];
    int tid = threadIdx.x;
    // P: exclusive prefix of g_us
    {
        float e0 = g_us[2*tid], e1 = g_us[2*tid+1];
        float cc = e0 + e1;
        c[tid] = cc; __syncthreads();
        for (int off = 1; off < 1024; off <<= 1) {
            float tv = c[tid];
            if (tid >= off) tv += c[tid - off];
            __syncthreads(); c[tid] = tv; __syncthreads();
        }
        float incl = c[tid];
        float excl = incl - cc;
        g_P[2*tid]   = excl;
        g_P[2*tid+1] = excl + e0;
        if (tid == 1023) g_P[SS] = incl;
        __syncthreads();
    }
    // Q: inclusive suffix of g_vs (as reversed prefix; avoids cancellation)
    {
        float d0 = g_vs[SS-1-2*tid];
        float d1 = g_vs[SS-2-2*tid];
        float cc = d0 + d1;
        c[tid] = cc; __syncthreads();
        for (int off = 1; off < 1024; off <<= 1) {
            float tv = c[tid];
            if (tid >= off) tv += c[tid - off];
            __syncthreads(); c[tid] = tv; __syncthreads();
        }
        float incl = c[tid];
        float excl = incl - cc;
        g_Q[SS - 2*tid]     = excl;
        g_Q[SS - (2*tid+1)] = excl + d0;
        if (tid == 1023) g_Q[0] = incl;
    }
}

// KD: per-chunk partial sums of u*f and v*f (direct gather from feat)
// grid (16, 16), block 256 = 4 chunks x 64 f
__global__ void kd_part(const float* __restrict__ feat) {
    int tid = threadIdx.x;
    int f  = tid & 63;
    int ch = blockIdx.y * 4 + (tid >> 6);
    int b  = blockIdx.x;
    int m0 = ch * CHM;
    const float* fb = feat + (size_t)b * SS * FF;
    float su = 0.f, sv = 0.f;
    #pragma unroll 8
    for (int m = m0; m < m0 + CHM; ++m) {
        float x = fb[(size_t)g_perm[m] * FF + f];
        su += g_us[m] * x;
        sv += g_vs[m] * x;
    }
    g_pu[(b*CH + ch)*FF + f] = su;
    g_pv[(b*CH + ch)*FF + f] = sv;
}

// KE: write G (exclusive prefix of u*f) and H (inclusive suffix of v*f)
// grid (16, 16), block 256 = 4 chunks x 64 f; gathered tile held in registers
__global__ void ke_write(const float* __restrict__ feat) {
    int tid = threadIdx.x;
    int f  = tid & 63;
    int ch = blockIdx.y * 4 + (tid >> 6);
    int b  = blockIdx.x;
    float offU = 0.f, offV = 0.f;
    for (int c2 = 0; c2 < CH; ++c2) {
        float pu = g_pu[(b*CH + c2)*FF + f];
        float pv = g_pv[(b*CH + c2)*FF + f];
        if (c2 < ch) offU += pu;
        if (c2 > ch) offV += pv;
    }
    int m0 = ch * CHM;
    const float* fb = feat + (size_t)b * SS * FF;
    float x[CHM];
    #pragma unroll
    for (int i = 0; i < CHM; ++i)
        x[i] = fb[(size_t)g_perm[m0 + i] * FF + f];
    float* Gb = g_G + (size_t)b * (SS+1) * FF;
    float* Hb = g_H + (size_t)b * (SS+1) * FF;
    float acc = offU;
    #pragma unroll
    for (int i = 0; i < CHM; ++i) {
        Gb[(size_t)(m0 + i) * FF + f] = acc;
        acc += g_us[m0 + i] * x[i];
    }
    float accV = offV;
    #pragma unroll
    for (int i = CHM - 1; i >= 0; --i) {
        accV += g_vs[m0 + i] * x[i];
        Hb[(size_t)(m0 + i) * FF + f] = accV;
    }
    if (ch == CH - 1) {
        Gb[(size_t)SS * FF + f] = acc;
        Hb[(size_t)SS * FF + f] = 0.f;
    }
}

// KF: main — per-warp coeffs (bsearch + Z), path row via smem-staged u/v with
// streaming stores, plus aligned row from G/H.
// grid RR/8, block 256 (8 warps, warp per row)
__global__ void __launch_bounds__(256) kf_main(const float* __restrict__ score,
                                               float* __restrict__ out) {
    __shared__ float4 su4[SS/4];   // 8 KB
    __shared__ float4 sv4[SS/4];   // 8 KB
    int tid = threadIdx.x;
    for (int i = tid; i < SS/4; i += 256) {
        su4[i] = reinterpret_cast<const float4*>(g_uo)[i];
        sv4[i] = reinterpret_cast<const float4*>(g_vo)[i];
    }
    __syncthreads();
    int warp = tid >> 5, lane = tid & 31;
    int r = blockIdx.x * 8 + warp;
    float s = score[r];
    int lo = 0, hi = SS;
    while (lo < hi) {
        int mid = (lo + hi) >> 1;
        if (g_ts[mid] <= s) lo = mid + 1; else hi = mid;
    }
    int k = lo;
    float e  = __expf(-s);
    float ei = __expf(s);
    float Z = e * g_P[k] + ei * g_Q[k];
    float inv = 1.0f / Z;
    float A  = e * inv;
    float Bv = ei * inv;

    float4* prow4 = reinterpret_cast<float4*>(out + (size_t)RR * FF + (size_t)r * SS);
    #pragma unroll 4
    for (int j4 = lane; j4 < SS/4; j4 += 32) {
        float4 u = su4[j4], v = sv4[j4];
        float4 p;
        p.x = fminf(A*u.x, Bv*v.x);
        p.y = fminf(A*u.y, Bv*v.y);
        p.z = fminf(A*u.z, Bv*v.z);
        p.w = fminf(A*u.w, Bv*v.w);
        __stcs(prow4 + j4, p);
    }

    int b = r >> 11;
    const float* Gp = g_G + ((size_t)b * (SS+1) + k) * FF;
    const float* Hp = g_H + ((size_t)b * (SS+1) + k) * FF;
    float2 g2 = *reinterpret_cast<const float2*>(Gp + 2*lane);
    float2 h2 = *reinterpret_cast<const float2*>(Hp + 2*lane);
    float2 o;
    o.x = A*g2.x + Bv*h2.x;
    o.y = A*g2.y + Bv*h2.y;
    *reinterpret_cast<float2*>(out + (size_t)r * FF + 2*lane) = o;
}

extern "C" void kernel_launch(void* const* d_in, const int* in_sizes, int n_in,
                              void* d_out, int out_size) {
    const float* score = (const float*)d_in[0];   // [16,2048,1]
    const float* feat  = (const float*)d_in[1];   // [16,2048,64]
    const float* tmpl  = (const float*)d_in[2];   // [1,2048,1]
    float* out = (float*)d_out;                   // aligned [16,2048,64] then path [16,2048,2048]

    ka_rank<<<SS/8, 256>>>(tmpl);
    kb_scan<<<1, 1024>>>();
    dim3 gp(BB, CH/4);
    kd_part<<<gp, 256>>>(feat);
    ke_write<<<gp, 256>>>(feat);
    kf_main<<<RR/8, 256>>>(score, out);
}